// round 7
// baseline (speedup 1.0000x reference)
#include <cuda_runtime.h>
#include <cuda_bf16.h>
#include <cstdint>

// LogicLayer: y[n, j] = c0[j] + c1[j]*a + c2[j]*b + c3[j]*a*b
//   (c0..c3) = softmax(weights[j,:16]) @ GATE_COEFS
//   a = x[n, idx_a[j]], b = x[n, idx_b[j]]   (idx int32 or int64, detected)
// x: [16384,4096] f32 -> y: [16384,4096] f32

#define IN_DIM   4096
#define OUT_DIM  4096
#define BATCH    16384
#define ROWS     4
#define THREADS  512
#define NWARPS   (THREADS / 32)             // 16
#define KSTEPS   (OUT_DIM / THREADS)        // 8
#define NWIN     (OUT_DIM / 32)             // 128 warp-windows of 32 j's

__device__ float4   g_coefp[OUT_DIM];       // permuted: index = win*32 + lane
__device__ unsigned g_meta [OUT_DIM];       // a(12) | b(12)<<12 | q(5)<<24

__constant__ float G0[16] = {0,0,0,0, 0,0,0,0, 1,1,1,1, 1,1,1,1};
__constant__ float G1[16] = {0,0,1,1, 0,0,1,1, -1,-1,0,0, -1,-1,0,0};
__constant__ float G2[16] = {0,0,0,0, 1,1,1,1, -1,-1,-1,-1, 0,0,0,0};
__constant__ float G3[16] = {0,1,-1,0, -1,0,-2,-1, 1,2,0,1, 0,1,-1,0};

__device__ __forceinline__ bool idx_is_i64(const int* p)
{
    bool i64 = true;
    #pragma unroll
    for (int i = 0; i < 16; ++i) {
        int lo = p[2 * i], hi = p[2 * i + 1];
        if (hi != 0 || (unsigned)lo >= IN_DIM) { i64 = false; break; }
    }
    return i64;
}
__device__ __forceinline__ int load_idx(const int* p, bool i64, int j)
{
    int v = i64 ? p[2 * j] : p[j];
    return (v < 0) ? 0 : (v >= IN_DIM ? IN_DIM - 1 : v);
}

// One warp per 32-j window. Lane q owns j = win*32+q. Softmax coefs in regs,
// then all lanes redundantly run a register-resident greedy assigning each j
// to one of 4 quarter-warp LDS phases, minimizing smem bank-group (idx&7)
// collisions for both gathers. One shfl per q (ga,gb packed).
__global__ void precompute_permute_kernel(const float* __restrict__ w,
                                          const int* __restrict__ ia,
                                          const int* __restrict__ ib)
{
    const int gtid = blockIdx.x * blockDim.x + threadIdx.x;
    const int win  = gtid >> 5;
    const int lane = gtid & 31;
    if (win >= NWIN) return;
    const int j = win * 32 + lane;

    const bool a64 = idx_is_i64(ia);
    const bool b64 = idx_is_i64(ib);
    const int ija = load_idx(ia, a64, j);
    const int ijb = load_idx(ib, b64, j);
    const int pk  = (ija & 7) | ((ijb & 7) << 3);

    // ---- softmax @ GATE_COEFS ----
    const float* wr = w + j * 16;
    float wv[16]; float m = -1e30f;
    #pragma unroll
    for (int i = 0; i < 16; ++i) { wv[i] = wr[i]; m = fmaxf(m, wv[i]); }
    float s = 0.f;
    #pragma unroll
    for (int i = 0; i < 16; ++i) { wv[i] = __expf(wv[i] - m); s += wv[i]; }
    float inv = 1.0f / s;
    float c0 = 0.f, c1 = 0.f, c2 = 0.f, c3 = 0.f;
    #pragma unroll
    for (int i = 0; i < 16; ++i) {
        float p = wv[i] * inv;
        c0 = fmaf(p, G0[i], c0); c1 = fmaf(p, G1[i], c1);
        c2 = fmaf(p, G2[i], c2); c3 = fmaf(p, G3[i], c3);
    }

    // ---- warp-synchronous greedy (identical in every lane, regs only) ----
    unsigned cntA[4] = {0,0,0,0};   // 8 groups x 4-bit counts per phase
    unsigned cntB[4] = {0,0,0,0};
    unsigned fill = 0;              // 4 x 8-bit phase fill
    int mylane = 0;
    #pragma unroll
    for (int q = 0; q < 32; ++q) {
        const int pkq = __shfl_sync(0xFFFFFFFFu, pk, q);  // independent shfls
        const int gaq = pkq & 7;
        const int gbq = (pkq >> 3) & 7;
        int bestp = 0, bestc = 1 << 30;
        #pragma unroll
        for (int p = 0; p < 4; ++p) {
            const int fp = (int)((fill >> (8 * p)) & 0xFF);
            int c = (fp >= 8) ? (1 << 29)
                  : 2 * (int)((cntA[p] >> (4 * gaq)) & 15u)
                  + 2 * (int)((cntB[p] >> (4 * gbq)) & 15u) + fp;
            if (c < bestc) { bestc = c; bestp = p; }
        }
        #pragma unroll
        for (int p = 0; p < 4; ++p) {
            if (p == bestp) { cntA[p] += 1u << (4 * gaq); cntB[p] += 1u << (4 * gbq); }
        }
        const int l = bestp * 8 + (int)((fill >> (8 * bestp)) & 0xFF);
        fill += 1u << (8 * bestp);
        if (lane == q) mylane = l;
    }

    g_coefp[win * 32 + mylane] = make_float4(c0, c1, c2, c3);
    g_meta [win * 32 + mylane] =
        (unsigned)ija | ((unsigned)ijb << 12) | ((unsigned)lane << 24);
}

// Main kernel: each block does ROWS=4 rows x all 4096 outputs.
// smem: x tile transposed as float4 per column: xs4[c] = {row0..row3}.
// Software-pipelined: coef/meta for step k+1 prefetched during step k.
__global__ __launch_bounds__(THREADS, 3)
void logic_main_kernel(const float* __restrict__ x, float* __restrict__ y)
{
    extern __shared__ float xs[];   // IN_DIM * ROWS floats (64 KB)

    const int row0 = blockIdx.x * ROWS;
    const int t    = threadIdx.x;
    const int lane = t & 31;
    const int w    = t >> 5;

    // ---- stage 4 rows transposed; LDG and STS fully coalesced ----
    {
        const int r  = lane & 3;
        const int cg = lane >> 2;
        const float* xrow = x + (size_t)(row0 + r) * IN_DIM;
        const int cbeg = w * (IN_DIM / NWARPS);        // 256 cols per warp
        #pragma unroll 4
        for (int base = cbeg; base < cbeg + (IN_DIM / NWARPS); base += 8) {
            int c = base + cg;
            xs[c * ROWS + r] = xrow[c];
        }
    }
    __syncthreads();

    const float4* __restrict__ xs4 = (const float4*)xs;
    float* __restrict__ y0 = y + (size_t)row0 * OUT_DIM;
    float* __restrict__ y1 = y0 + OUT_DIM;
    float* __restrict__ y2 = y1 + OUT_DIM;
    float* __restrict__ y3 = y2 + OUT_DIM;

    int j0 = (w << 5);                        // warp's current 32-j window
    float4   cf = g_coefp[j0 + lane];
    unsigned mt = g_meta [j0 + lane];

    #pragma unroll
    for (int kk = 0; kk < KSTEPS; ++kk) {
        float4   cfn;
        unsigned mtn;
        if (kk < KSTEPS - 1) {                // prefetch next step
            cfn = g_coefp[j0 + THREADS + lane];
            mtn = g_meta [j0 + THREADS + lane];
        }

        const float4 a = xs4[mt & 0xFFFu];
        const float4 b = xs4[(mt >> 12) & 0xFFFu];
        const float c0 = cf.x, c1 = cf.y, c2 = cf.z, c3 = cf.w;
        // y = (c0 + c1*a) + b*(c2 + c3*a)
        float o0 = fmaf(b.x, fmaf(c3, a.x, c2), fmaf(c1, a.x, c0));
        float o1 = fmaf(b.y, fmaf(c3, a.y, c2), fmaf(c1, a.y, c0));
        float o2 = fmaf(b.z, fmaf(c3, a.z, c2), fmaf(c1, a.z, c0));
        float o3 = fmaf(b.w, fmaf(c3, a.w, c2), fmaf(c1, a.w, c0));
        const int col = j0 + (int)(mt >> 24);  // permuted within 128B segment
        y0[col] = o0;
        y1[col] = o1;
        y2[col] = o2;
        y3[col] = o3;

        j0 += THREADS;
        cf = cfn;
        mt = mtn;
    }
}

extern "C" void kernel_launch(void* const* d_in, const int* in_sizes, int n_in,
                              void* d_out, int out_size)
{
    const float* x  = (const float*)d_in[0];
    const float* wt = (const float*)d_in[1];
    const int*   ia = (const int*)d_in[2];
    const int*   ib = (const int*)d_in[3];
    float*       y  = (float*)d_out;

    cudaFuncSetAttribute(logic_main_kernel,
                         cudaFuncAttributeMaxDynamicSharedMemorySize,
                         IN_DIM * ROWS * (int)sizeof(float));

    precompute_permute_kernel<<<(NWIN * 32 + THREADS - 1) / THREADS, THREADS>>>(wt, ia, ib);

    const int smem = IN_DIM * ROWS * (int)sizeof(float);
    logic_main_kernel<<<BATCH / ROWS, THREADS, smem>>>(x, y);
}

// round 8
// speedup vs baseline: 1.2608x; 1.2608x over previous
#include <cuda_runtime.h>
#include <cuda_bf16.h>
#include <cstdint>

// LogicLayer: y[n, j] = c0[j] + c1[j]*a + c2[j]*b + c3[j]*a*b
//   (c0..c3) = softmax(weights[j,:16]) @ GATE_COEFS
//   a = x[n, idx_a[j]], b = x[n, idx_b[j]]   (idx int32 or int64, detected)
// x: [16384,4096] f32 -> y: [16384,4096] f32

#define IN_DIM   4096
#define OUT_DIM  4096
#define BATCH    16384
#define ROWS     4
#define THREADS  512
#define NWARPS   (THREADS / 32)             // 16
#define KSTEPS   (OUT_DIM / THREADS)        // 8
#define NWIN     (OUT_DIM / 32)             // 128 warp-windows of 32 j's

__device__ float4   g_coefp[OUT_DIM];       // permuted: index = win*32 + lane
__device__ unsigned g_meta [OUT_DIM];       // a(12) | b(12)<<12 | q(5)<<24

__constant__ float G0[16] = {0,0,0,0, 0,0,0,0, 1,1,1,1, 1,1,1,1};
__constant__ float G1[16] = {0,0,1,1, 0,0,1,1, -1,-1,0,0, -1,-1,0,0};
__constant__ float G2[16] = {0,0,0,0, 1,1,1,1, -1,-1,-1,-1, 0,0,0,0};
__constant__ float G3[16] = {0,1,-1,0, -1,0,-2,-1, 1,2,0,1, 0,1,-1,0};

__device__ __forceinline__ bool idx_is_i64(const int* p)
{
    bool i64 = true;
    #pragma unroll
    for (int i = 0; i < 16; ++i) {
        int lo = p[2 * i], hi = p[2 * i + 1];
        if (hi != 0 || (unsigned)lo >= IN_DIM) { i64 = false; break; }
    }
    return i64;
}
__device__ __forceinline__ int load_idx(const int* p, bool i64, int j)
{
    int v = i64 ? p[2 * j] : p[j];
    return (v < 0) ? 0 : (v >= IN_DIM ? IN_DIM - 1 : v);
}

// One warp per 32-j window. Lane q owns j = win*32+q. Softmax coefs in regs,
// then all lanes redundantly run a register-resident greedy assigning each j
// to one of 4 quarter-warp LDS phases, minimizing smem bank-group (idx&7)
// collisions for both gathers. One shfl per q (ga,gb packed).
__global__ void precompute_permute_kernel(const float* __restrict__ w,
                                          const int* __restrict__ ia,
                                          const int* __restrict__ ib)
{
    const int gtid = blockIdx.x * blockDim.x + threadIdx.x;
    const int win  = gtid >> 5;
    const int lane = gtid & 31;
    if (win >= NWIN) return;
    const int j = win * 32 + lane;

    const bool a64 = idx_is_i64(ia);
    const bool b64 = idx_is_i64(ib);
    const int ija = load_idx(ia, a64, j);
    const int ijb = load_idx(ib, b64, j);
    const int pk  = (ija & 7) | ((ijb & 7) << 3);

    // ---- softmax @ GATE_COEFS ----
    const float* wr = w + j * 16;
    float wv[16]; float m = -1e30f;
    #pragma unroll
    for (int i = 0; i < 16; ++i) { wv[i] = wr[i]; m = fmaxf(m, wv[i]); }
    float s = 0.f;
    #pragma unroll
    for (int i = 0; i < 16; ++i) { wv[i] = __expf(wv[i] - m); s += wv[i]; }
    float inv = 1.0f / s;
    float c0 = 0.f, c1 = 0.f, c2 = 0.f, c3 = 0.f;
    #pragma unroll
    for (int i = 0; i < 16; ++i) {
        float p = wv[i] * inv;
        c0 = fmaf(p, G0[i], c0); c1 = fmaf(p, G1[i], c1);
        c2 = fmaf(p, G2[i], c2); c3 = fmaf(p, G3[i], c3);
    }

    // ---- warp-synchronous greedy (identical in every lane, regs only) ----
    unsigned cntA[4] = {0,0,0,0};   // 8 groups x 4-bit counts per phase
    unsigned cntB[4] = {0,0,0,0};
    unsigned fill = 0;              // 4 x 8-bit phase fill
    int mylane = 0;
    #pragma unroll
    for (int q = 0; q < 32; ++q) {
        const int pkq = __shfl_sync(0xFFFFFFFFu, pk, q);
        const int gaq = pkq & 7;
        const int gbq = (pkq >> 3) & 7;
        int bestp = 0, bestc = 1 << 30;
        #pragma unroll
        for (int p = 0; p < 4; ++p) {
            const int fp = (int)((fill >> (8 * p)) & 0xFF);
            int c = (fp >= 8) ? (1 << 29)
                  : 2 * (int)((cntA[p] >> (4 * gaq)) & 15u)
                  + 2 * (int)((cntB[p] >> (4 * gbq)) & 15u) + fp;
            if (c < bestc) { bestc = c; bestp = p; }
        }
        #pragma unroll
        for (int p = 0; p < 4; ++p) {
            if (p == bestp) { cntA[p] += 1u << (4 * gaq); cntB[p] += 1u << (4 * gbq); }
        }
        const int l = bestp * 8 + (int)((fill >> (8 * bestp)) & 0xFF);
        fill += 1u << (8 * bestp);
        if (lane == q) mylane = l;
    }

    g_coefp[win * 32 + mylane] = make_float4(c0, c1, c2, c3);
    g_meta [win * 32 + mylane] =
        (unsigned)ija | ((unsigned)ijb << 12) | ((unsigned)lane << 24);
}

// Main kernel: each block does ROWS=4 rows x all 4096 outputs.
// smem: x tile transposed as float4 per column: xs4[c] = {row0..row3}.
// Staging uses register transpose: 4 dense LDG.32 (1 wavefront each) +
// 1 conflict-free STS.128 per column, instead of scattered LDG (4 wf/instr).
__global__ __launch_bounds__(THREADS, 3)
void logic_main_kernel(const float* __restrict__ x, float* __restrict__ y)
{
    extern __shared__ float xs[];   // IN_DIM * ROWS floats (64 KB)
    float4* __restrict__ xs4w = (float4*)xs;

    const int row0 = blockIdx.x * ROWS;
    const int t    = threadIdx.x;
    const int lane = t & 31;
    const int w    = t >> 5;

    // ---- stage 4 rows via register transpose ----
    {
        const float* xr = x + (size_t)row0 * IN_DIM;
        const int cbeg = w * (IN_DIM / NWARPS);        // 256 cols per warp
        #pragma unroll
        for (int i = 0; i < (IN_DIM / NWARPS) / 32; ++i) {   // 8 iters
            const int c = cbeg + i * 32 + lane;
            float v0 = xr[c];
            float v1 = xr[c + IN_DIM];
            float v2 = xr[c + 2 * IN_DIM];
            float v3 = xr[c + 3 * IN_DIM];
            xs4w[c] = make_float4(v0, v1, v2, v3);
        }
    }
    __syncthreads();

    const float4* __restrict__ xs4 = (const float4*)xs;
    float* __restrict__ y0 = y + (size_t)row0 * OUT_DIM;
    float* __restrict__ y1 = y0 + OUT_DIM;
    float* __restrict__ y2 = y1 + OUT_DIM;
    float* __restrict__ y3 = y2 + OUT_DIM;

    #pragma unroll
    for (int kk = 0; kk < KSTEPS; ++kk) {
        const int j0 = kk * THREADS + (w << 5);        // warp's 32-j window
        const float4   cf = g_coefp[j0 + lane];
        const unsigned mt = g_meta [j0 + lane];
        const float4 a = xs4[mt & 0xFFFu];
        const float4 b = xs4[(mt >> 12) & 0xFFFu];
        const float c0 = cf.x, c1 = cf.y, c2 = cf.z, c3 = cf.w;
        // y = (c0 + c1*a) + b*(c2 + c3*a)
        float o0 = fmaf(b.x, fmaf(c3, a.x, c2), fmaf(c1, a.x, c0));
        float o1 = fmaf(b.y, fmaf(c3, a.y, c2), fmaf(c1, a.y, c0));
        float o2 = fmaf(b.z, fmaf(c3, a.z, c2), fmaf(c1, a.z, c0));
        float o3 = fmaf(b.w, fmaf(c3, a.w, c2), fmaf(c1, a.w, c0));
        const int col = j0 + (int)(mt >> 24);          // permuted in 128B seg
        y0[col] = o0;
        y1[col] = o1;
        y2[col] = o2;
        y3[col] = o3;
    }
}

extern "C" void kernel_launch(void* const* d_in, const int* in_sizes, int n_in,
                              void* d_out, int out_size)
{
    const float* x  = (const float*)d_in[0];
    const float* wt = (const float*)d_in[1];
    const int*   ia = (const int*)d_in[2];
    const int*   ib = (const int*)d_in[3];
    float*       y  = (float*)d_out;

    cudaFuncSetAttribute(logic_main_kernel,
                         cudaFuncAttributeMaxDynamicSharedMemorySize,
                         IN_DIM * ROWS * (int)sizeof(float));

    precompute_permute_kernel<<<(NWIN * 32 + THREADS - 1) / THREADS, THREADS>>>(wt, ia, ib);

    const int smem = IN_DIM * ROWS * (int)sizeof(float);
    logic_main_kernel<<<BATCH / ROWS, THREADS, smem>>>(x, y);
}